// round 1
// baseline (speedup 1.0000x reference)
#include <cuda_runtime.h>
#include <math.h>

// Shapes (fixed by the problem)
#define BB   4
#define TT   2048
#define CC   1024
#define NH   16
#define HD   64
#define MM   (BB*TT)          // 8192 rows
#define N_QKV (3*CC)          // 3072

// ---------------------------------------------------------------------------
// Scratch (device globals; no allocation allowed)
// ---------------------------------------------------------------------------
__device__ float g_Q[BB*NH*TT*HD];   // (B,H,T,D) 32MB
__device__ float g_K[BB*NH*TT*HD];
__device__ float g_V[BB*NH*TT*HD];
__device__ float g_O[MM*CC];         // (B,T,C)   32MB

// ---------------------------------------------------------------------------
// Kernel 1: QKV GEMM  (x[8192,1024] @ W_qkv[1024,3072] + b) -> scatter Q/K/V
// 128x128x8 tile, 256 threads, 8x8 per-thread microtile
// ---------------------------------------------------------------------------
__global__ __launch_bounds__(256) void sgemm_qkv(const float* __restrict__ A,
                                                 const float* __restrict__ W,
                                                 const float* __restrict__ bias) {
    __shared__ float As[8][128];   // transposed A tile
    __shared__ float Bs[8][128];

    const int tid  = threadIdx.x;
    const int crow = blockIdx.y * 128;
    const int ccol = blockIdx.x * 128;
    const int tr   = tid >> 4;      // 0..15
    const int tc   = tid & 15;      // 0..15

    const int arow = tid >> 1;          // 0..127
    const int acol = (tid & 1) * 4;     // 0 or 4
    const int brow = tid >> 5;          // 0..7
    const int bcol = (tid & 31) * 4;    // 0..124

    float acc[8][8];
    #pragma unroll
    for (int i = 0; i < 8; i++)
        #pragma unroll
        for (int j = 0; j < 8; j++) acc[i][j] = 0.0f;

    const float* Aptr = A + (size_t)crow * CC;
    const float* Wptr = W + ccol;

    for (int k0 = 0; k0 < CC; k0 += 8) {
        float4 a4 = *(const float4*)(Aptr + (size_t)arow * CC + k0 + acol);
        As[acol+0][arow] = a4.x;
        As[acol+1][arow] = a4.y;
        As[acol+2][arow] = a4.z;
        As[acol+3][arow] = a4.w;
        *(float4*)&Bs[brow][bcol] = *(const float4*)(Wptr + (size_t)(k0+brow) * N_QKV + bcol);
        __syncthreads();
        #pragma unroll
        for (int k = 0; k < 8; k++) {
            float ra[8], rb[8];
            *(float4*)&ra[0] = *(float4*)&As[k][tr*8];
            *(float4*)&ra[4] = *(float4*)&As[k][tr*8+4];
            *(float4*)&rb[0] = *(float4*)&Bs[k][tc*8];
            *(float4*)&rb[4] = *(float4*)&Bs[k][tc*8+4];
            #pragma unroll
            for (int i = 0; i < 8; i++)
                #pragma unroll
                for (int j = 0; j < 8; j++)
                    acc[i][j] += ra[i] * rb[j];
        }
        __syncthreads();
    }

    // Epilogue: bias + scatter into (B,H,T,D)
    #pragma unroll
    for (int i = 0; i < 8; i++) {
        int m = crow + tr*8 + i;
        int b = m >> 11;           // /2048
        int t = m & 2047;
        #pragma unroll
        for (int j = 0; j < 8; j++) {
            int n = ccol + tc*8 + j;
            float v = acc[i][j] + bias[n];
            int which = n >> 10;   // 0=q 1=k 2=v
            int c = n & 1023;
            int h = c >> 6;
            int d = c & 63;
            float* dst = (which == 0) ? g_Q : (which == 1) ? g_K : g_V;
            dst[(((size_t)(b*NH + h) * TT) + t) * HD + d] = v;
        }
    }
}

// ---------------------------------------------------------------------------
// Kernel 2: causal flash attention, fp32.
// Block: 256 threads (16x16), 64 queries x 64 keys per tile, head_dim 64.
// sKP buffer holds K^T during QK, then P during PV (exactly 48KB smem total).
// ---------------------------------------------------------------------------
__global__ __launch_bounds__(256) void flash_kernel() {
    __shared__ float sQt[64*64];   // Q^T: [d][i], pre-scaled
    __shared__ float sKP[64*64];   // K^T: [d][j]  -> reused as P: [i][j]
    __shared__ float sV [64*64];   // V:   [j][d]

    const int tid = threadIdx.x;
    const int tx  = tid & 15;      // key-col / dim group
    const int ty  = tid >> 4;      // query-row group
    const int qt  = blockIdx.x;    // query tile (0..31)
    const int bh  = blockIdx.y;    // b*16 + h

    const float scale = 0.125f;    // 1/sqrt(64)

    const float* qbase = g_Q + ((size_t)bh * TT + qt*64) * HD;

    // load Q transposed + scaled
    for (int idx = tid; idx < 64*16; idx += 256) {
        int i  = idx >> 4;
        int d4 = (idx & 15) << 2;
        float4 v = *(const float4*)(qbase + i*HD + d4);
        sQt[(d4+0)*64 + i] = v.x * scale;
        sQt[(d4+1)*64 + i] = v.y * scale;
        sQt[(d4+2)*64 + i] = v.z * scale;
        sQt[(d4+3)*64 + i] = v.w * scale;
    }

    float o[4][4];
    float m[4], l[4];
    #pragma unroll
    for (int r = 0; r < 4; r++) {
        m[r] = -INFINITY; l[r] = 0.0f;
        #pragma unroll
        for (int d = 0; d < 4; d++) o[r][d] = 0.0f;
    }

    for (int kt = 0; kt <= qt; kt++) {
        __syncthreads();   // prior-iter readers of sKP/sV done; also covers sQt first time
        const float* kbase = g_K + ((size_t)bh * TT + kt*64) * HD;
        const float* vbase = g_V + ((size_t)bh * TT + kt*64) * HD;
        for (int idx = tid; idx < 64*16; idx += 256) {
            int i  = idx >> 4;
            int d4 = (idx & 15) << 2;
            float4 v = *(const float4*)(kbase + i*HD + d4);
            sKP[(d4+0)*64 + i] = v.x;
            sKP[(d4+1)*64 + i] = v.y;
            sKP[(d4+2)*64 + i] = v.z;
            sKP[(d4+3)*64 + i] = v.w;
        }
        for (int idx = tid; idx < 1024; idx += 256)
            ((float4*)sV)[idx] = ((const float4*)vbase)[idx];
        __syncthreads();

        // S = Q K^T (4x4 per thread)
        float s[4][4];
        #pragma unroll
        for (int r = 0; r < 4; r++)
            #pragma unroll
            for (int c = 0; c < 4; c++) s[r][c] = 0.0f;

        #pragma unroll 16
        for (int d = 0; d < 64; d++) {
            float4 qv = *(float4*)&sQt[d*64 + 4*ty];
            float4 kv = *(float4*)&sKP[d*64 + 4*tx];
            float qa[4] = {qv.x, qv.y, qv.z, qv.w};
            float ka[4] = {kv.x, kv.y, kv.z, kv.w};
            #pragma unroll
            for (int r = 0; r < 4; r++)
                #pragma unroll
                for (int c = 0; c < 4; c++)
                    s[r][c] += qa[r] * ka[c];
        }

        // causal mask on diagonal tile
        if (kt == qt) {
            #pragma unroll
            for (int r = 0; r < 4; r++)
                #pragma unroll
                for (int c = 0; c < 4; c++)
                    if (4*tx + c > 4*ty + r) s[r][c] = -INFINITY;
        }

        // online softmax update (row stats over the 16 tx lanes)
        float corr[4];
        #pragma unroll
        for (int r = 0; r < 4; r++) {
            float mx = fmaxf(fmaxf(s[r][0], s[r][1]), fmaxf(s[r][2], s[r][3]));
            #pragma unroll
            for (int off = 8; off > 0; off >>= 1)
                mx = fmaxf(mx, __shfl_xor_sync(0xffffffffu, mx, off, 16));
            float mnew = fmaxf(m[r], mx);
            corr[r] = __expf(m[r] - mnew);
            m[r] = mnew;
            float rs = 0.0f;
            #pragma unroll
            for (int c = 0; c < 4; c++) {
                float p = __expf(s[r][c] - mnew);
                s[r][c] = p;
                rs += p;
            }
            #pragma unroll
            for (int off = 8; off > 0; off >>= 1)
                rs += __shfl_xor_sync(0xffffffffu, rs, off, 16);
            l[r] = l[r] * corr[r] + rs;
            #pragma unroll
            for (int d = 0; d < 4; d++) o[r][d] *= corr[r];
        }

        // write P into sKP (natural [row][col] layout)
        __syncthreads();
        #pragma unroll
        for (int r = 0; r < 4; r++) {
            float4 pv = make_float4(s[r][0], s[r][1], s[r][2], s[r][3]);
            *(float4*)&sKP[(4*ty + r)*64 + 4*tx] = pv;
        }
        __syncthreads();

        // O += P V
        #pragma unroll 8
        for (int j = 0; j < 64; j++) {
            float4 vv = *(float4*)&sV[j*64 + 4*tx];
            float va[4] = {vv.x, vv.y, vv.z, vv.w};
            #pragma unroll
            for (int r = 0; r < 4; r++) {
                float p = sKP[(4*ty + r)*64 + j];
                #pragma unroll
                for (int d = 0; d < 4; d++) o[r][d] += p * va[d];
            }
        }
    }

    // epilogue: normalize, write to (B,T,C) layout
    const int b = bh >> 4;
    const int h = bh & 15;
    float* obase = g_O + ((size_t)b * TT + qt*64) * CC + h*HD;
    #pragma unroll
    for (int r = 0; r < 4; r++) {
        float inv = 1.0f / l[r];
        float4 v = make_float4(o[r][0]*inv, o[r][1]*inv, o[r][2]*inv, o[r][3]*inv);
        *(float4*)(obase + (size_t)(4*ty + r) * CC + 4*tx) = v;
    }
}

// ---------------------------------------------------------------------------
// Kernel 3: output projection  g_O[8192,1024] @ W_out[1024,1024] + b -> d_out
// ---------------------------------------------------------------------------
__global__ __launch_bounds__(256) void sgemm_out(const float* __restrict__ W,
                                                 const float* __restrict__ bias,
                                                 float* __restrict__ C) {
    __shared__ float As[8][128];
    __shared__ float Bs[8][128];

    const int tid  = threadIdx.x;
    const int crow = blockIdx.y * 128;
    const int ccol = blockIdx.x * 128;
    const int tr   = tid >> 4;
    const int tc   = tid & 15;

    const int arow = tid >> 1;
    const int acol = (tid & 1) * 4;
    const int brow = tid >> 5;
    const int bcol = (tid & 31) * 4;

    float acc[8][8];
    #pragma unroll
    for (int i = 0; i < 8; i++)
        #pragma unroll
        for (int j = 0; j < 8; j++) acc[i][j] = 0.0f;

    const float* Aptr = g_O + (size_t)crow * CC;
    const float* Wptr = W + ccol;

    for (int k0 = 0; k0 < CC; k0 += 8) {
        float4 a4 = *(const float4*)(Aptr + (size_t)arow * CC + k0 + acol);
        As[acol+0][arow] = a4.x;
        As[acol+1][arow] = a4.y;
        As[acol+2][arow] = a4.z;
        As[acol+3][arow] = a4.w;
        *(float4*)&Bs[brow][bcol] = *(const float4*)(Wptr + (size_t)(k0+brow) * CC + bcol);
        __syncthreads();
        #pragma unroll
        for (int k = 0; k < 8; k++) {
            float ra[8], rb[8];
            *(float4*)&ra[0] = *(float4*)&As[k][tr*8];
            *(float4*)&ra[4] = *(float4*)&As[k][tr*8+4];
            *(float4*)&rb[0] = *(float4*)&Bs[k][tc*8];
            *(float4*)&rb[4] = *(float4*)&Bs[k][tc*8+4];
            #pragma unroll
            for (int i = 0; i < 8; i++)
                #pragma unroll
                for (int j = 0; j < 8; j++)
                    acc[i][j] += ra[i] * rb[j];
        }
        __syncthreads();
    }

    #pragma unroll
    for (int i = 0; i < 8; i++) {
        int mrow = crow + tr*8 + i;
        #pragma unroll
        for (int j4 = 0; j4 < 8; j4 += 4) {
            int n0 = ccol + tc*8 + j4;
            float4 v = make_float4(acc[i][j4+0] + bias[n0+0],
                                   acc[i][j4+1] + bias[n0+1],
                                   acc[i][j4+2] + bias[n0+2],
                                   acc[i][j4+3] + bias[n0+3]);
            *(float4*)(C + (size_t)mrow * CC + n0) = v;
        }
    }
}

// ---------------------------------------------------------------------------
extern "C" void kernel_launch(void* const* d_in, const int* in_sizes, int n_in,
                              void* d_out, int out_size) {
    const float* x     = (const float*)d_in[0];
    const float* W_qkv = (const float*)d_in[1];
    const float* b_qkv = (const float*)d_in[2];
    const float* W_out = (const float*)d_in[3];
    const float* b_out = (const float*)d_in[4];
    float* out = (float*)d_out;

    dim3 gQKV(N_QKV/128, MM/128);          // 24 x 64
    sgemm_qkv<<<gQKV, 256>>>(x, W_qkv, b_qkv);

    dim3 gFA(TT/64, BB*NH);                // 32 x 64
    flash_kernel<<<gFA, 256>>>();

    dim3 gOUT(CC/128, MM/128);             // 8 x 64
    sgemm_out<<<gOUT, 256>>>(W_out, b_out, out);
}

// round 3
// speedup vs baseline: 3.2223x; 3.2223x over previous
#include <cuda_runtime.h>
#include <math.h>
#include <stdint.h>

// Shapes (fixed by the problem)
#define BB   4
#define TT   2048
#define CC   1024
#define NH   16
#define HD   64
#define MM   (BB*TT)          // 8192 rows
#define N_QKV (3*CC)          // 3072

// ---------------------------------------------------------------------------
// Scratch (device globals; no allocation allowed)
// ---------------------------------------------------------------------------
__device__ float g_Q[BB*NH*TT*HD];   // (B,H,T,D)
__device__ float g_K[BB*NH*TT*HD];
__device__ float g_V[BB*NH*TT*HD];
__device__ float g_O[MM*CC];         // (B,T,C)

// ---------------------------------------------------------------------------
// Helpers: tf32 convert + m16n8k8 tf32 MMA
// ---------------------------------------------------------------------------
__device__ __forceinline__ uint32_t f2tf32(float f) {
    uint32_t r;
    asm("cvt.rna.tf32.f32 %0, %1;" : "=r"(r) : "f"(f));
    return r;
}

__device__ __forceinline__ void mma8(float c[4], const uint32_t a[4],
                                     uint32_t b0, uint32_t b1) {
    asm volatile(
        "mma.sync.aligned.m16n8k8.row.col.f32.tf32.tf32.f32 "
        "{%0,%1,%2,%3},{%4,%5,%6,%7},{%8,%9},{%0,%1,%2,%3};"
        : "+f"(c[0]), "+f"(c[1]), "+f"(c[2]), "+f"(c[3])
        : "r"(a[0]), "r"(a[1]), "r"(a[2]), "r"(a[3]), "r"(b0), "r"(b1));
}

// ---------------------------------------------------------------------------
// TF32 tensor-core GEMM: C[M,N] = A[M,K] @ W[K,N] + bias   (K = CC = 1024)
// BM=128 BN=128 BK=16, 256 threads (8 warps, 4x2), warp tile 32x64.
// Smem pads: A rows padded to 20 (conflict-free A-frag reads),
//            B rows padded to 136 (conflict-free B-frag reads).
// MODE 0: A = x (arg), epilogue scatters into g_Q/g_K/g_V.
// MODE 1: A = g_O (device symbol, resolved in device code!), plain store.
// ---------------------------------------------------------------------------
#define PADA 20
#define PADB 136

template <int MODE>
__global__ __launch_bounds__(256) void sgemm_tc(const float* __restrict__ Aarg,
                                                const float* __restrict__ W,
                                                const float* __restrict__ bias,
                                                float* __restrict__ C,
                                                int N) {
    __shared__ uint32_t As[2][128 * PADA];
    __shared__ uint32_t Bs[2][16 * PADB];

    // NOTE: device-symbol A selected HERE (host cannot pass g_O's address).
    const float* A = (MODE == 1) ? (const float*)g_O : Aarg;

    const int tid  = threadIdx.x;
    const int lane = tid & 31;
    const int g    = lane >> 2;      // 0..7
    const int q    = lane & 3;       // 0..3
    const int wid  = tid >> 5;       // 0..7
    const int wm   = (wid & 3) * 32; // warp row offset
    const int wn   = (wid >> 2) * 64;// warp col offset

    const int bm = blockIdx.y * 128;
    const int bn = blockIdx.x * 128;

    // global-load assignments
    const int lrow = tid >> 1;           // 0..127 (A row)
    const int lcg  = (tid & 1) * 8;      // A col group (0 or 8)
    const int brow = tid >> 4;           // 0..15  (B row)
    const int bcg  = (tid & 15) * 8;     // B col group

    const float* Ap = A + (size_t)(bm + lrow) * CC + lcg;
    const float* Wp = W + (size_t)brow * N + bn + bcg;

    float c[2][8][4];
    #pragma unroll
    for (int mt = 0; mt < 2; mt++)
        #pragma unroll
        for (int nt = 0; nt < 8; nt++)
            #pragma unroll
            for (int r = 0; r < 4; r++) c[mt][nt][r] = 0.0f;

    // prologue: load tile 0
    {
        float4 a0 = *(const float4*)(Ap);
        float4 a1 = *(const float4*)(Ap + 4);
        float4 b0 = *(const float4*)(Wp);
        float4 b1 = *(const float4*)(Wp + 4);
        uint32_t* as = &As[0][lrow * PADA + lcg];
        as[0]=f2tf32(a0.x); as[1]=f2tf32(a0.y); as[2]=f2tf32(a0.z); as[3]=f2tf32(a0.w);
        as[4]=f2tf32(a1.x); as[5]=f2tf32(a1.y); as[6]=f2tf32(a1.z); as[7]=f2tf32(a1.w);
        uint32_t* bs = &Bs[0][brow * PADB + bcg];
        bs[0]=f2tf32(b0.x); bs[1]=f2tf32(b0.y); bs[2]=f2tf32(b0.z); bs[3]=f2tf32(b0.w);
        bs[4]=f2tf32(b1.x); bs[5]=f2tf32(b1.y); bs[6]=f2tf32(b1.z); bs[7]=f2tf32(b1.w);
    }

    const int NT = CC / 16;   // 64 k-tiles
    for (int t = 0; t < NT; t++) {
        __syncthreads();
        const int buf = t & 1;

        float4 a0, a1, b0, b1;
        if (t + 1 < NT) {
            const float* ap = Ap + (t + 1) * 16;
            const float* wp = Wp + (size_t)(t + 1) * 16 * N;
            a0 = *(const float4*)(ap);
            a1 = *(const float4*)(ap + 4);
            b0 = *(const float4*)(wp);
            b1 = *(const float4*)(wp + 4);
        }

        #pragma unroll
        for (int kk = 0; kk < 16; kk += 8) {
            uint32_t af[2][4];
            #pragma unroll
            for (int mt = 0; mt < 2; mt++) {
                const int rb = wm + mt * 16;
                af[mt][0] = As[buf][(rb + g)     * PADA + kk + q];
                af[mt][1] = As[buf][(rb + g + 8) * PADA + kk + q];
                af[mt][2] = As[buf][(rb + g)     * PADA + kk + q + 4];
                af[mt][3] = As[buf][(rb + g + 8) * PADA + kk + q + 4];
            }
            #pragma unroll
            for (int nt = 0; nt < 8; nt++) {
                uint32_t bf0 = Bs[buf][(kk + q)     * PADB + wn + nt * 8 + g];
                uint32_t bf1 = Bs[buf][(kk + q + 4) * PADB + wn + nt * 8 + g];
                mma8(c[0][nt], af[0], bf0, bf1);
                mma8(c[1][nt], af[1], bf0, bf1);
            }
        }

        if (t + 1 < NT) {
            const int nb = (t + 1) & 1;
            uint32_t* as = &As[nb][lrow * PADA + lcg];
            as[0]=f2tf32(a0.x); as[1]=f2tf32(a0.y); as[2]=f2tf32(a0.z); as[3]=f2tf32(a0.w);
            as[4]=f2tf32(a1.x); as[5]=f2tf32(a1.y); as[6]=f2tf32(a1.z); as[7]=f2tf32(a1.w);
            uint32_t* bs = &Bs[nb][brow * PADB + bcg];
            bs[0]=f2tf32(b0.x); bs[1]=f2tf32(b0.y); bs[2]=f2tf32(b0.z); bs[3]=f2tf32(b0.w);
            bs[4]=f2tf32(b1.x); bs[5]=f2tf32(b1.y); bs[6]=f2tf32(b1.z); bs[7]=f2tf32(b1.w);
        }
    }

    // epilogue
    #pragma unroll
    for (int mt = 0; mt < 2; mt++) {
        #pragma unroll
        for (int nt = 0; nt < 8; nt++) {
            #pragma unroll
            for (int r = 0; r < 4; r++) {
                int row = bm + wm + mt * 16 + g + (r >> 1) * 8;
                int col = bn + wn + nt * 8 + q * 2 + (r & 1);
                float v = c[mt][nt][r] + bias[col];
                if (MODE == 0) {
                    // scatter into (B,H,T,D)
                    int b = row >> 11;
                    int tt = row & 2047;
                    int which = col >> 10;
                    int cc = col & 1023;
                    int h = cc >> 6;
                    int d = cc & 63;
                    float* dst = (which == 0) ? g_Q : (which == 1) ? g_K : g_V;
                    dst[(((size_t)(b * NH + h) * TT) + tt) * HD + d] = v;
                } else {
                    C[(size_t)row * N + col] = v;
                }
            }
        }
    }
}

// ---------------------------------------------------------------------------
// Flash attention, tf32 tensor cores.
// Block: 128 threads (4 warps), 64 queries; each warp owns 16 query rows,
// all 64 key cols -> no cross-warp softmax. KV tiles of 64 keys.
// Q fragments register-resident. P round-trips through smem (own rows only,
// so no barrier between P write and PV mma).
// ---------------------------------------------------------------------------
#define KP 68
#define VP 72
#define PP 68
#define FLASH_SMEM ((64*KP + 64*VP + 64*PP) * 4)

__global__ __launch_bounds__(128) void flash_tc() {
    extern __shared__ uint32_t sm[];
    uint32_t* Ks = sm;
    uint32_t* Vs = sm + 64 * KP;
    uint32_t* Ps = sm + 64 * KP + 64 * VP;

    const int tid  = threadIdx.x;
    const int lane = tid & 31;
    const int g    = lane >> 2;
    const int q    = lane & 3;
    const int w    = tid >> 5;
    const int wrow = w * 16;

    const int qt = blockIdx.x;      // query tile
    const int bh = blockIdx.y;      // b*16 + h
    const float scale = 0.125f;     // 1/sqrt(64)

    // Q fragments: 8 k-steps x 4 regs, pre-scaled, tf32
    const float* Qp = g_Q + ((size_t)bh * TT + qt * 64) * HD;
    uint32_t qa[8][4];
    #pragma unroll
    for (int ks = 0; ks < 8; ks++) {
        const int r0 = wrow + g, r1 = wrow + g + 8;
        const int c0 = ks * 8 + q, c1 = c0 + 4;
        qa[ks][0] = f2tf32(Qp[r0 * HD + c0] * scale);
        qa[ks][1] = f2tf32(Qp[r1 * HD + c0] * scale);
        qa[ks][2] = f2tf32(Qp[r0 * HD + c1] * scale);
        qa[ks][3] = f2tf32(Qp[r1 * HD + c1] * scale);
    }

    float o[8][4];
    #pragma unroll
    for (int nt = 0; nt < 8; nt++)
        #pragma unroll
        for (int r = 0; r < 4; r++) o[nt][r] = 0.0f;
    float m0 = -INFINITY, m1 = -INFINITY, l0 = 0.0f, l1 = 0.0f;

    for (int kt = 0; kt <= qt; kt++) {
        __syncthreads();
        const float* Kp = g_K + ((size_t)bh * TT + kt * 64) * HD;
        const float* Vp = g_V + ((size_t)bh * TT + kt * 64) * HD;
        for (int idx = tid; idx < 64 * 16; idx += 128) {
            const int r  = idx >> 4;
            const int c4 = (idx & 15) * 4;
            float4 kv = *(const float4*)(Kp + r * HD + c4);
            float4 vv = *(const float4*)(Vp + r * HD + c4);
            uint32_t* kd = &Ks[r * KP + c4];
            kd[0]=f2tf32(kv.x); kd[1]=f2tf32(kv.y); kd[2]=f2tf32(kv.z); kd[3]=f2tf32(kv.w);
            uint32_t* vd = &Vs[r * VP + c4];
            vd[0]=f2tf32(vv.x); vd[1]=f2tf32(vv.y); vd[2]=f2tf32(vv.z); vd[3]=f2tf32(vv.w);
        }
        __syncthreads();

        // S = Q K^T
        float s[8][4];
        #pragma unroll
        for (int nt = 0; nt < 8; nt++)
            #pragma unroll
            for (int r = 0; r < 4; r++) s[nt][r] = 0.0f;

        #pragma unroll
        for (int kk = 0; kk < 8; kk++) {
            #pragma unroll
            for (int nt = 0; nt < 8; nt++) {
                uint32_t b0 = Ks[(nt * 8 + g) * KP + kk * 8 + q];
                uint32_t b1 = Ks[(nt * 8 + g) * KP + kk * 8 + q + 4];
                mma8(s[nt], qa[kk], b0, b1);
            }
        }

        // causal mask on diagonal tile
        if (kt == qt) {
            const int r0 = wrow + g, r1 = wrow + g + 8;
            #pragma unroll
            for (int nt = 0; nt < 8; nt++) {
                const int c0 = nt * 8 + q * 2;
                if (c0     > r0) s[nt][0] = -INFINITY;
                if (c0 + 1 > r0) s[nt][1] = -INFINITY;
                if (c0     > r1) s[nt][2] = -INFINITY;
                if (c0 + 1 > r1) s[nt][3] = -INFINITY;
            }
        }

        // online softmax (rows g, g+8; reduce across 4 lanes of the quad)
        float mx0 = -INFINITY, mx1 = -INFINITY;
        #pragma unroll
        for (int nt = 0; nt < 8; nt++) {
            mx0 = fmaxf(mx0, fmaxf(s[nt][0], s[nt][1]));
            mx1 = fmaxf(mx1, fmaxf(s[nt][2], s[nt][3]));
        }
        mx0 = fmaxf(mx0, __shfl_xor_sync(0xffffffffu, mx0, 1));
        mx0 = fmaxf(mx0, __shfl_xor_sync(0xffffffffu, mx0, 2));
        mx1 = fmaxf(mx1, __shfl_xor_sync(0xffffffffu, mx1, 1));
        mx1 = fmaxf(mx1, __shfl_xor_sync(0xffffffffu, mx1, 2));

        float mn0 = fmaxf(m0, mx0), mn1 = fmaxf(m1, mx1);
        float corr0 = __expf(m0 - mn0), corr1 = __expf(m1 - mn1);
        m0 = mn0; m1 = mn1;

        float rs0 = 0.0f, rs1 = 0.0f;
        #pragma unroll
        for (int nt = 0; nt < 8; nt++) {
            s[nt][0] = __expf(s[nt][0] - m0); rs0 += s[nt][0];
            s[nt][1] = __expf(s[nt][1] - m0); rs0 += s[nt][1];
            s[nt][2] = __expf(s[nt][2] - m1); rs1 += s[nt][2];
            s[nt][3] = __expf(s[nt][3] - m1); rs1 += s[nt][3];
        }
        rs0 += __shfl_xor_sync(0xffffffffu, rs0, 1);
        rs0 += __shfl_xor_sync(0xffffffffu, rs0, 2);
        rs1 += __shfl_xor_sync(0xffffffffu, rs1, 1);
        rs1 += __shfl_xor_sync(0xffffffffu, rs1, 2);
        l0 = l0 * corr0 + rs0;
        l1 = l1 * corr1 + rs1;

        #pragma unroll
        for (int nt = 0; nt < 8; nt++) {
            o[nt][0] *= corr0; o[nt][1] *= corr0;
            o[nt][2] *= corr1; o[nt][3] *= corr1;
        }

        // P -> smem (tf32). Each warp writes & reads only its own 16 rows:
        // no barrier needed.
        #pragma unroll
        for (int nt = 0; nt < 8; nt++) {
            const int c0 = nt * 8 + q * 2;
            Ps[(wrow + g)     * PP + c0    ] = f2tf32(s[nt][0]);
            Ps[(wrow + g)     * PP + c0 + 1] = f2tf32(s[nt][1]);
            Ps[(wrow + g + 8) * PP + c0    ] = f2tf32(s[nt][2]);
            Ps[(wrow + g + 8) * PP + c0 + 1] = f2tf32(s[nt][3]);
        }

        // O += P V
        #pragma unroll
        for (int kk = 0; kk < 8; kk++) {
            uint32_t a[4];
            a[0] = Ps[(wrow + g)     * PP + kk * 8 + q];
            a[1] = Ps[(wrow + g + 8) * PP + kk * 8 + q];
            a[2] = Ps[(wrow + g)     * PP + kk * 8 + q + 4];
            a[3] = Ps[(wrow + g + 8) * PP + kk * 8 + q + 4];
            #pragma unroll
            for (int nt = 0; nt < 8; nt++) {
                uint32_t b0 = Vs[(kk * 8 + q)     * VP + nt * 8 + g];
                uint32_t b1 = Vs[(kk * 8 + q + 4) * VP + nt * 8 + g];
                mma8(o[nt], a, b0, b1);
            }
        }
    }

    // epilogue -> g_O in (B,T,C)
    const float inv0 = 1.0f / l0, inv1 = 1.0f / l1;
    const int b = bh >> 4;
    const int h = bh & 15;
    float* obase = g_O + ((size_t)b * TT + qt * 64) * CC + h * HD;
    const int r0 = wrow + g, r1 = wrow + g + 8;
    #pragma unroll
    for (int nt = 0; nt < 8; nt++) {
        const int col = nt * 8 + q * 2;
        float2 v0 = make_float2(o[nt][0] * inv0, o[nt][1] * inv0);
        float2 v1 = make_float2(o[nt][2] * inv1, o[nt][3] * inv1);
        *(float2*)(obase + (size_t)r0 * CC + col) = v0;
        *(float2*)(obase + (size_t)r1 * CC + col) = v1;
    }
}

// ---------------------------------------------------------------------------
extern "C" void kernel_launch(void* const* d_in, const int* in_sizes, int n_in,
                              void* d_out, int out_size) {
    const float* x     = (const float*)d_in[0];
    const float* W_qkv = (const float*)d_in[1];
    const float* b_qkv = (const float*)d_in[2];
    const float* W_out = (const float*)d_in[3];
    const float* b_out = (const float*)d_in[4];
    float* out = (float*)d_out;

    static bool attr_set = false;
    if (!attr_set) {
        cudaFuncSetAttribute(flash_tc,
                             cudaFuncAttributeMaxDynamicSharedMemorySize,
                             FLASH_SMEM);
        attr_set = true;
    }

    dim3 gQKV(N_QKV / 128, MM / 128);      // 24 x 64
    sgemm_tc<0><<<gQKV, 256>>>(x, W_qkv, b_qkv, nullptr, N_QKV);

    dim3 gFA(TT / 64, BB * NH);            // 32 x 64
    flash_tc<<<gFA, 128, FLASH_SMEM>>>();

    dim3 gOUT(CC / 128, MM / 128);         // 8 x 64
    sgemm_tc<1><<<gOUT, 256>>>(nullptr, W_out, b_out, out, CC);
}